// round 17
// baseline (speedup 1.0000x reference)
#include <cuda_runtime.h>
#include <cuda_fp16.h>
#include <stdint.h>

#define NROWS 16384
#define KSPLIT 8
#define TILES (128 * KSPLIT)     // 1024
#define CHUNK (NROWS / KSPLIT)   // 2048 keys per chunk
#define NIT   (CHUNK / 64)       // 32 inner iterations
#define GRID_ATTN 148
#define LOG2E 1.4426950408889634f

// ---------------- scratch (device globals; no allocation allowed) ----------------
__device__ float  g_X  [NROWS * 128];          // layer output / next-layer input
__device__ __half g_G  [NROWS * 64];           // graph-learn projection (fp16)
__device__ float  g_SQ [NROWS];                // L * t * |g16|^2   (pre-scaled!)
__device__ __half g_H  [NROWS * 128];          // gnn projection (fp16)
__device__ __half g_HR [NROWS * 128];          // fp32-fp16 residual of H
__device__ float  g_PO [(size_t)KSPLIT * NROWS * 128];  // partial O per keychunk
__device__ float  g_PRS[(size_t)KSPLIT * NROWS];        // partial rowsums

// ---------------- asm helpers ----------------
__device__ __forceinline__ void mma_16816(float (&c)[4], const uint32_t (&a)[4],
                                          uint32_t b0, uint32_t b1) {
    asm volatile(
        "mma.sync.aligned.m16n8k16.row.col.f32.f16.f16.f32 "
        "{%0,%1,%2,%3},{%4,%5,%6,%7},{%8,%9},{%0,%1,%2,%3};\n"
        : "+f"(c[0]), "+f"(c[1]), "+f"(c[2]), "+f"(c[3])
        : "r"(a[0]), "r"(a[1]), "r"(a[2]), "r"(a[3]), "r"(b0), "r"(b1));
}
__device__ __forceinline__ void ldsm4(uint32_t &r0, uint32_t &r1, uint32_t &r2, uint32_t &r3,
                                      uint32_t addr) {
    asm volatile("ldmatrix.sync.aligned.m8n8.x4.shared.b16 {%0,%1,%2,%3},[%4];\n"
                 : "=r"(r0), "=r"(r1), "=r"(r2), "=r"(r3) : "r"(addr));
}
__device__ __forceinline__ void ldsm4t(uint32_t &r0, uint32_t &r1, uint32_t &r2, uint32_t &r3,
                                       uint32_t addr) {
    asm volatile("ldmatrix.sync.aligned.m8n8.x4.trans.shared.b16 {%0,%1,%2,%3},[%4];\n"
                 : "=r"(r0), "=r"(r1), "=r"(r2), "=r"(r3) : "r"(addr));
}
__device__ __forceinline__ void cp16(uint32_t dst, const void* src) {
    asm volatile("cp.async.cg.shared.global [%0], [%1], 16;\n" :: "r"(dst), "l"(src));
}
#define CP_COMMIT() asm volatile("cp.async.commit_group;\n" ::: "memory")
#define CP_WAIT1()  asm volatile("cp.async.wait_group 1;\n" ::: "memory")

__device__ __forceinline__ float ex2_approx(float x) {
    float y; asm("ex2.approx.f32 %0, %1;\n" : "=f"(y) : "f"(x)); return y;
}
__device__ __forceinline__ float rcp_approx(float x) {
    float y; asm("rcp.approx.f32 %0, %1;\n" : "=f"(y) : "f"(x)); return y;
}
// p = sigma(x) with A = -log2e * x precomputed upstream: u = 2^A, p = 1/(1+u).
// fp32 end-to-end (R7 lesson). Branch-free (R13 lesson).

// ---------------- fused projection kernel ----------------
// One pass over X[N,128]: G = relu(X@Wg+Bg) -> fp16 + L*t*|g16|^2, and
// H = X@Wh+Bh -> fp16 + fp16 residual (h32 - h16).
__global__ __launch_bounds__(256) void proj_fused_kernel(
    const float* __restrict__ X,
    const float* __restrict__ Wg, const float* __restrict__ Bg,
    const float* __restrict__ Wh, const float* __restrict__ Bh,
    const float* __restrict__ tempp,
    __half* __restrict__ G, float* __restrict__ SQ,
    __half* __restrict__ H, __half* __restrict__ HR)
{
    __shared__ __align__(16) float Xs [32 * 132];
    __shared__ __align__(16) float Wgs[32 * 64];
    __shared__ __align__(16) float Whs[32 * 128];

    const int tid  = threadIdx.x;
    const int lane = tid & 31;
    const int wy   = tid >> 5;
    const int rowbase = blockIdx.x * 32;
    const float Lt = LOG2E * (1.0f + *tempp);

    #pragma unroll
    for (int i = tid; i < 32 * 32; i += 256) {
        int r = i >> 5, c = i & 31;
        ((float4*)(Xs + r * 132))[c] =
            ((const float4*)(X + (size_t)(rowbase + r) * 128))[c];
    }

    float accg[4][2], acch[4][4];
    #pragma unroll
    for (int rs = 0; rs < 4; rs++) {
        accg[rs][0] = accg[rs][1] = 0.f;
        #pragma unroll
        for (int cs = 0; cs < 4; cs++) acch[rs][cs] = 0.f;
    }

    for (int kc = 0; kc < 128; kc += 32) {
        __syncthreads();
        #pragma unroll
        for (int i = tid; i < 512; i += 256)
            ((float4*)Wgs)[i] = ((const float4*)(Wg + (size_t)kc * 64))[i];
        #pragma unroll
        for (int i = tid; i < 1024; i += 256)
            ((float4*)Whs)[i] = ((const float4*)(Wh + (size_t)kc * 128))[i];
        __syncthreads();

        #pragma unroll
        for (int k4 = 0; k4 < 8; k4++) {
            float4 xv[4];
            #pragma unroll
            for (int rs = 0; rs < 4; rs++)
                xv[rs] = *(const float4*)(Xs + (wy + rs * 8) * 132 + kc + k4 * 4);
            #pragma unroll
            for (int kk = 0; kk < 4; kk++) {
                const int k = k4 * 4 + kk;
                float2 wg2 = *(const float2*)(Wgs + k * 64 + lane * 2);
                float4 wh4 = *(const float4*)(Whs + k * 128 + lane * 4);
                #pragma unroll
                for (int rs = 0; rs < 4; rs++) {
                    float xk = ((const float*)&xv[rs])[kk];
                    accg[rs][0] = fmaf(xk, wg2.x, accg[rs][0]);
                    accg[rs][1] = fmaf(xk, wg2.y, accg[rs][1]);
                    acch[rs][0] = fmaf(xk, wh4.x, acch[rs][0]);
                    acch[rs][1] = fmaf(xk, wh4.y, acch[rs][1]);
                    acch[rs][2] = fmaf(xk, wh4.z, acch[rs][2]);
                    acch[rs][3] = fmaf(xk, wh4.w, acch[rs][3]);
                }
            }
        }
    }

    #pragma unroll
    for (int rs = 0; rs < 4; rs++) {
        const int row = rowbase + wy + rs * 8;
        float ssq = 0.f;
        #pragma unroll
        for (int cs = 0; cs < 2; cs++) {
            int col = lane * 2 + cs;
            float v = fmaxf(accg[rs][cs] + Bg[col], 0.f);
            __half h = __float2half_rn(v);
            G[(size_t)row * 64 + col] = h;
            float vh = __half2float(h);
            ssq += vh * vh;
        }
        #pragma unroll
        for (int off = 16; off; off >>= 1) ssq += __shfl_xor_sync(0xffffffffu, ssq, off);
        if (lane == 0) SQ[row] = Lt * ssq;
        #pragma unroll
        for (int cs = 0; cs < 4; cs++) {
            int col = lane * 4 + cs;
            float v = acch[rs][cs] + Bh[col];
            __half h = __float2half_rn(v);
            H[(size_t)row * 128 + col] = h;
            HR[(size_t)row * 128 + col] = __float2half_rn(v - __half2float(h));
        }
    }
}

// ---------------- fused sigmoid-attention kernel (persistent, key-split) ----------------
// partialO[kc] += sigmoid(t*(2 g_i.g_j - sq_i - sq_j) + th) @ h ; partialRS[kc] += rowsum
// Software-pipelined across tiles: iter 'it' computes S+sigmoid(tile it) and runs
// the O-MMAs of tile it-1 (P packed last iter, no data stall). 4-stage smem ring.
// Occupancy 1 (R12), branch-free fp32 sigmoid (R7/R13).

// dynamic smem (bytes): 4 stages of {K 64x72 f16, H 64x136 f16, SQ 64 f32}
#define OFF_K(b)   ((b) * 9216)
#define OFF_H(b)   (36864 + (b) * 17408)
#define OFF_SQ(b)  (106496 + (b) * 256)
#define SMEM_BYTES 107520

__global__ __launch_bounds__(256, 1) void attn_kernel(
    const __half* __restrict__ G, const float* __restrict__ SQ,
    const __half* __restrict__ H,
    const float* __restrict__ tempp, const float* __restrict__ thetap,
    float* __restrict__ PO, float* __restrict__ PRS)
{
    extern __shared__ __align__(16) char dsm[];
    const uint32_t smem_u32 = (uint32_t)__cvta_generic_to_shared(dsm);

    const int tid  = threadIdx.x;
    const int lane = tid & 31;
    const int warp = tid >> 5;
    const int gid  = lane >> 2;
    const int qid  = lane & 3;

    const float tt  = 1.0f + *tempp;          // t
    const float th  = 5.0f + *thetap;
    const float a2  = -2.0f * tt * LOG2E;     // coefficient of S in A = -L*x
    const float Lth = LOG2E * th;
    const uint32_t ONES = 0x3C003C00u;

    const uint32_t* G32 = reinterpret_cast<const uint32_t*>(G);

    for (int t = blockIdx.x; t < TILES; t += GRID_ATTN) {
        const int rb = t & 127;
        const int kc = t >> 7;
        const int keybase = kc * CHUNK;
        const int rowbase = rb * 128 + warp * 16;
        const int r0 = rowbase + gid, r1 = r0 + 8;

        // Q fragments
        uint32_t aq[4][4];
        #pragma unroll
        for (int ks = 0; ks < 4; ks++) {
            int c0 = ks * 8 + qid;
            aq[ks][0] = G32[(size_t)r0 * 32 + c0];
            aq[ks][1] = G32[(size_t)r1 * 32 + c0];
            aq[ks][2] = G32[(size_t)r0 * 32 + c0 + 4];
            aq[ks][3] = G32[(size_t)r1 * 32 + c0 + 4];
        }
        // ci' = L*t*sq_i - L*th  (SQ is pre-scaled by L*t)
        const float ci0 = SQ[r0] - Lth;
        const float ci1 = SQ[r1] - Lth;

        float accO[16][4];
        #pragma unroll
        for (int i = 0; i < 16; i++)
            #pragma unroll
            for (int j = 0; j < 4; j++) accO[i][j] = 0.f;
        float rsacc[4] = {0.f, 0.f, 0.f, 0.f};

        uint32_t pPo[8][2];   // P of tile it-1 (consumed by delayed O-phase)
        uint32_t pPn[8][2];   // P of tile it

        // ---- async tile loader (stage b = it & 3) ----
        auto issue = [&](int it2) {
            if (it2 < NIT) {
                const int b = it2 & 3;
                const int j0 = keybase + it2 * 64;
                uint32_t kdst = smem_u32 + OFF_K(b);
                const char* ksrc = (const char*)(G + (size_t)j0 * 64);
                #pragma unroll
                for (int i = tid; i < 512; i += 256) {
                    int r = i >> 3, c = i & 7;
                    cp16(kdst + (r * 72 + c * 8) * 2, ksrc + i * 16);
                }
                uint32_t hdst = smem_u32 + OFF_H(b);
                const char* hsrc = (const char*)(H + (size_t)j0 * 128);
                #pragma unroll
                for (int i = tid; i < 1024; i += 256) {
                    int r = i >> 4, c = i & 15;
                    cp16(hdst + (r * 136 + c * 8) * 2, hsrc + i * 16);
                }
                if (tid < 16)
                    cp16(smem_u32 + OFF_SQ(b) + tid * 16, (const char*)(SQ + j0) + tid * 16);
            }
        };

        // ---- S-phase for one nb block: S-MMA + sigmoid + pack ----
        auto sphase = [&](int nb, uint32_t skb, const float* sqb, uint32_t (&dst)[2]) {
            float c4[4] = {0.f, 0.f, 0.f, 0.f};
            uint32_t b0, b1, b2, b3, b4, b5, b6, b7;
            uint32_t addr = skb + ((nb * 8 + (lane & 7)) * 72 + (lane >> 3) * 8) * 2;
            ldsm4(b0, b1, b2, b3, addr);
            ldsm4(b4, b5, b6, b7, addr + 64);
            mma_16816(c4, aq[0], b0, b1);
            mma_16816(c4, aq[1], b2, b3);
            mma_16816(c4, aq[2], b4, b5);
            mma_16816(c4, aq[3], b6, b7);

            float vj0 = sqb[nb * 8 + qid * 2];       // L*t*sq_j
            float vj1 = sqb[nb * 8 + qid * 2 + 1];
            float u00 = ex2_approx(fmaf(a2, c4[0], ci0 + vj0));
            float u01 = ex2_approx(fmaf(a2, c4[1], ci0 + vj1));
            float u10 = ex2_approx(fmaf(a2, c4[2], ci1 + vj0));
            float u11 = ex2_approx(fmaf(a2, c4[3], ci1 + vj1));
            float p00 = rcp_approx(1.0f + u00);
            float p01 = rcp_approx(1.0f + u01);
            float p10 = rcp_approx(1.0f + u10);
            float p11 = rcp_approx(1.0f + u11);

            __half2 ph0 = __floats2half2_rn(p00, p01);
            __half2 ph1 = __floats2half2_rn(p10, p11);
            dst[0] = *reinterpret_cast<uint32_t*>(&ph0);
            dst[1] = *reinterpret_cast<uint32_t*>(&ph1);
        };

        // ---- O-phase for one ks: rowsum + 16 O-MMAs from given P pair ----
        auto ophase = [&](int ks, uint32_t shb, const uint32_t (&P)[8][2]) {
            uint32_t ap[4] = { P[2*ks][0], P[2*ks][1], P[2*ks+1][0], P[2*ks+1][1] };
            mma_16816(rsacc, ap, ONES, ONES);
            #pragma unroll
            for (int np = 0; np < 8; np++) {
                uint32_t h0, h1, h2, h3;
                uint32_t addr = shb +
                    ((ks * 16 + ((lane >> 3) & 1) * 8 + (lane & 7)) * 136 +
                     np * 16 + (lane >> 4) * 8) * 2;
                ldsm4t(h0, h1, h2, h3, addr);
                mma_16816(accO[2 * np],     ap, h0, h1);
                mma_16816(accO[2 * np + 1], ap, h2, h3);
            }
        };

        issue(0); CP_COMMIT();
        issue(1); CP_COMMIT();

        // ---- peeled iter 0: S-phase only (fills pPo) ----
        {
            CP_WAIT1();
            __syncthreads();
            issue(2); CP_COMMIT();
            const uint32_t skb = smem_u32 + OFF_K(0);
            const float* sqb = (const float*)(dsm + OFF_SQ(0));
            #pragma unroll
            for (int nb = 0; nb < 8; nb++) sphase(nb, skb, sqb, pPo[nb]);
        }

        // ---- main loop: S(it) interleaved with O(it-1) ----
        for (int it = 1; it < NIT; it++) {
            const int b  = it & 3;
            const int bo = (it - 1) & 3;

            CP_WAIT1();          // tile(it) resident
            __syncthreads();     // all warps past reads of buf (it+2)&3's previous life
            issue(it + 2);
            CP_COMMIT();

            const uint32_t skb = smem_u32 + OFF_K(b);
            const uint32_t shb = smem_u32 + OFF_H(bo);
            const float* sqb = (const float*)(dsm + OFF_SQ(b));

            #pragma unroll
            for (int ks = 0; ks < 4; ks++) {
                sphase(2 * ks,     skb, sqb, pPn[2 * ks]);
                sphase(2 * ks + 1, skb, sqb, pPn[2 * ks + 1]);
                ophase(ks, shb, pPo);           // tile it-1: P ready, no stall
            }
            #pragma unroll
            for (int nb = 0; nb < 8; nb++) {
                pPo[nb][0] = pPn[nb][0];
                pPo[nb][1] = pPn[nb][1];
            }
        }

        // ---- epilogue: O-phase of last tile ----
        {
            const uint32_t shb = smem_u32 + OFF_H((NIT - 1) & 3);
            #pragma unroll
            for (int ks = 0; ks < 4; ks++) ophase(ks, shb, pPo);
        }

        // ---- store partial O and rowsums ----
        float* po = PO + (size_t)kc * NROWS * 128;
        #pragma unroll
        for (int nb = 0; nb < 16; nb++) {
            int c0 = nb * 8 + qid * 2;
            *(float2*)(po + (size_t)r0 * 128 + c0) = make_float2(accO[nb][0], accO[nb][1]);
            *(float2*)(po + (size_t)r1 * 128 + c0) = make_float2(accO[nb][2], accO[nb][3]);
        }
        if (qid == 0) {
            PRS[(size_t)kc * NROWS + r0] = rsacc[0];
            PRS[(size_t)kc * NROWS + r1] = rsacc[2];
        }
        __syncthreads();   // keep stage buffers quiescent across chunk transition
    }
}

// ---------------- combine: sum partials, diag residual, normalize, relu ----------------
__global__ __launch_bounds__(256) void combine_kernel(
    const float* __restrict__ PO, const float* __restrict__ PRS,
    const __half* __restrict__ HR, const float* __restrict__ thetap,
    float* __restrict__ X, int do_relu)
{
    const int row = blockIdx.x * 2 + (threadIdx.x >> 7);
    const int col = threadIdx.x & 127;
    const float th = 5.0f + *thetap;
    const float pd = 1.0f / (1.0f + expf(-th));

    float acc = 0.f, rs = 0.f;
    #pragma unroll
    for (int k = 0; k < KSPLIT; k++) {
        acc += PO[((size_t)k * NROWS + row) * 128 + col];
        rs  += PRS[(size_t)k * NROWS + row];
    }
    float hr = __half2float(HR[(size_t)row * 128 + col]);
    float v = fmaf(pd, hr, acc) / rs;
    if (do_relu) v = fmaxf(v, 0.f);
    X[(size_t)row * 128 + col] = v;
}

// ---------------- final projection (128->10) + softmax ----------------
__global__ __launch_bounds__(256) void out_kernel(
    const float* __restrict__ X, const float* __restrict__ W,
    const float* __restrict__ B, float* __restrict__ out)
{
    int gw = (blockIdx.x * blockDim.x + threadIdx.x) >> 5;
    int lane = threadIdx.x & 31;
    if (gw >= NROWS) return;
    const float* x = X + (size_t)gw * 128;
    float xv0 = x[lane], xv1 = x[lane + 32], xv2 = x[lane + 64], xv3 = x[lane + 96];
    float lg[10];
    #pragma unroll
    for (int c = 0; c < 10; c++) {
        float s = xv0 * W[lane * 10 + c] + xv1 * W[(lane + 32) * 10 + c]
                + xv2 * W[(lane + 64) * 10 + c] + xv3 * W[(lane + 96) * 10 + c];
        #pragma unroll
        for (int off = 16; off; off >>= 1) s += __shfl_xor_sync(0xffffffffu, s, off);
        lg[c] = s + B[c];
    }
    if (lane == 0) {
        float mx = lg[0];
        #pragma unroll
        for (int c = 1; c < 10; c++) mx = fmaxf(mx, lg[c]);
        float den = 0.f, e[10];
        #pragma unroll
        for (int c = 0; c < 10; c++) { e[c] = expf(lg[c] - mx); den += e[c]; }
        float inv = 1.0f / den;
        #pragma unroll
        for (int c = 0; c < 10; c++) out[(size_t)gw * 10 + c] = e[c] * inv;
    }
}

// ---------------- launch ----------------
extern "C" void kernel_launch(void* const* d_in, const int* in_sizes, int n_in,
                              void* d_out, int out_size)
{
    const float* feat   = (const float*)d_in[0];
    const float* gl_w0  = (const float*)d_in[1];
    const float* gl_b0  = (const float*)d_in[2];
    const float* gl_w1  = (const float*)d_in[3];
    const float* gl_b1  = (const float*)d_in[4];
    const float* gnn_w0 = (const float*)d_in[5];
    const float* gnn_b0 = (const float*)d_in[6];
    const float* gnn_w1 = (const float*)d_in[7];
    const float* gnn_b1 = (const float*)d_in[8];
    const float* out_w  = (const float*)d_in[9];
    const float* out_b  = (const float*)d_in[10];
    const float* temp   = (const float*)d_in[11];
    const float* theta  = (const float*)d_in[12];

    float*  Xp;  cudaGetSymbolAddress((void**)&Xp,  g_X);
    __half* Gp;  cudaGetSymbolAddress((void**)&Gp,  g_G);
    float*  SQp; cudaGetSymbolAddress((void**)&SQp, g_SQ);
    __half* Hp;  cudaGetSymbolAddress((void**)&Hp,  g_H);
    __half* HRp; cudaGetSymbolAddress((void**)&HRp, g_HR);
    float*  POp; cudaGetSymbolAddress((void**)&POp, g_PO);
    float*  PRSp;cudaGetSymbolAddress((void**)&PRSp,g_PRS);

    static bool attr_set = false;
    if (!attr_set) {
        cudaFuncSetAttribute(attn_kernel, cudaFuncAttributeMaxDynamicSharedMemorySize,
                             SMEM_BYTES);
        attr_set = true;
    }

    // layer 1
    proj_fused_kernel<<<NROWS / 32, 256>>>(feat, gl_w0, gl_b0, gnn_w0, gnn_b0, temp,
                                           Gp, SQp, Hp, HRp);
    attn_kernel<<<GRID_ATTN, 256, SMEM_BYTES>>>(Gp, SQp, Hp, temp, theta, POp, PRSp);
    combine_kernel<<<NROWS / 2, 256>>>(POp, PRSp, HRp, theta, Xp, 1);

    // layer 2
    proj_fused_kernel<<<NROWS / 32, 256>>>(Xp, gl_w1, gl_b1, gnn_w1, gnn_b1, temp,
                                           Gp, SQp, Hp, HRp);
    attn_kernel<<<GRID_ATTN, 256, SMEM_BYTES>>>(Gp, SQp, Hp, temp, theta, POp, PRSp);
    combine_kernel<<<NROWS / 2, 256>>>(POp, PRSp, HRp, theta, Xp, 0);

    // output head + softmax
    out_kernel<<<NROWS * 32 / 256, 256>>>(Xp, out_w, out_b, (float*)d_out);
}